// round 1
// baseline (speedup 1.0000x reference)
#include <cuda_runtime.h>
#include <math.h>

// ---------------------------------------------------------------------------
// KAN generator:
//   h0 = relu(x @ lin_w.T + lin_b)            [512,16] -> [512,4,2,2]
//   h1 = kan_conv(up2(h0), w1)                [512,4,4,4]
//   h2 = kan_conv(up2(h1), w2)                [512,4,8,8]
//   h3 = kan_conv(up2(h2), w3)                [512,4,16,16]
//   out = tanh(kan_conv(up2(h3), w4))         [512,3,32,32]
//
// kan_conv: patches (3x3, pad 1, channel-major c*9+ky*3+kx), per-value
// features = [relu(v), B-spline bases b2_0..b2_4(v)] (grid 3, order 2,
// uniform knots on [-1,1]); out = features . weights.
//
// Optimization structure:
//  * features computed ONCE per source value (pre-upsample) into SMEM
//  * up2 collapses the 3x3 patch to a 2x2 set of distinct source pixels;
//    the 9 taps are pre-summed into parity-dependent combined weights
//  * zero-padding contributes spline(0) != 0: precomputed pad vectors
// ---------------------------------------------------------------------------

__device__ float g_h0[512 * 16];
__device__ float g_h1[512 * 64];
__device__ float g_h2[512 * 256];
__device__ float g_h3[512 * 1024];

__device__ __forceinline__ void spline_feats(float v, float* out /*6*/) {
    const float H = 2.0f / 3.0f;
    float g[8];
#pragma unroll
    for (int i = 0; i < 8; i++) g[i] = (float)(i - 2) * H - 1.0f;
    float b0[7];
#pragma unroll
    for (int i = 0; i < 7; i++)
        b0[i] = (v >= g[i] && v < g[i + 1]) ? 1.0f : 0.0f;
    float b1[6];
#pragma unroll
    for (int i = 0; i < 6; i++)
        b1[i] = (v - g[i]) * (1.0f / (g[i + 1] - g[i])) * b0[i]
              + (g[i + 2] - v) * (1.0f / (g[i + 2] - g[i + 1])) * b0[i + 1];
    float b2[5];
#pragma unroll
    for (int i = 0; i < 5; i++)
        b2[i] = (v - g[i]) * (1.0f / (g[i + 2] - g[i])) * b1[i]
              + (g[i + 3] - v) * (1.0f / (g[i + 3] - g[i + 1])) * b1[i + 1];
    out[0] = fmaxf(v, 0.0f);
#pragma unroll
    for (int i = 0; i < 5; i++) out[1 + i] = b2[i];
}

// ----------------------------- linear + relu -------------------------------
__global__ void lin_relu_kernel(const float* __restrict__ x,
                                const float* __restrict__ w,
                                const float* __restrict__ b,
                                float* __restrict__ out) {
    int idx = blockIdx.x * blockDim.x + threadIdx.x;  // 8192 = 512*16
    if (idx >= 512 * 16) return;
    int bi = idx >> 4, j = idx & 15;
    const float4* xr = reinterpret_cast<const float4*>(x + bi * 100);
    const float4* wr = reinterpret_cast<const float4*>(w + j * 100);
    float acc = b[j];
#pragma unroll
    for (int k = 0; k < 25; k++) {
        float4 a = xr[k], q = wr[k];
        acc += a.x * q.x + a.y * q.y + a.z * q.z + a.w * q.w;
    }
    out[idx] = fmaxf(acc, 0.0f);
}

// ----------------------------- fused up2 + KAN conv ------------------------
// One block handles IMGS = 256/HIN^2 images: 1024 source values, 256 output
// quads (each thread = one 2x2 output quad aligned to the upsampling grid).
template <int HIN, int COUT, bool FINAL>
__global__ __launch_bounds__(256) void kan_stage_kernel(
    const float* __restrict__ hin,       // [N_img, 4, HIN, HIN]
    const float* __restrict__ base_w,    // [COUT, 36]
    const float* __restrict__ spline_w,  // [COUT, 36, 5]
    float* __restrict__ hout)            // [N_img, COUT, 2*HIN, 2*HIN]
{
    constexpr int S2   = HIN * HIN;
    constexpr int IMGS = 256 / S2;
    constexpr int NSRC = IMGS * 4 * S2;  // 1024
    constexpr int HOUT = 2 * HIN;

    __shared__ float  feat[NSRC * 7];    // 28 KB, f-stride 7 (conflict-free)
    __shared__ float4 wsh4[4 * 4 * 4 * 6];  // [p][pos][c][f] -> float4 over co
    __shared__ float4 psh4[16];             // [p][pos] pad contribution
    float* wsh = reinterpret_cast<float*>(wsh4);

    const int tid = threadIdx.x;

    // Phase A: featurize 4 source values per thread
#pragma unroll
    for (int k = 0; k < 4; k++) {
        int lv = tid + k * 256;
        float v = hin[(size_t)blockIdx.x * NSRC + lv];
        spline_feats(v, &feat[lv * 7]);
    }

    // Phase B: combined weights  W[p][pos][c][f][co]
    // pixel parity p=(py,px), source offset pos=(ry,rx); tap set per (parity,r):
    //   start = r*(1+parity), count = 1 + (r ^ parity)
    for (int e = tid; e < 4 * 4 * 4 * 6 * 4; e += 256) {
        int co  = e & 3;
        int f   = (e >> 2) % 6;
        int c   = (e / 24) & 3;
        int pos = (e / 96) & 3;
        int p   = e / 384;
        int py = p >> 1, px = p & 1;
        int ry = pos >> 1, rx = pos & 1;
        float s = 0.0f;
        if (co < COUT) {
            int ky0 = ry * (1 + py), nky = 1 + (ry ^ py);
            int kx0 = rx * (1 + px), nkx = 1 + (rx ^ px);
            for (int a = 0; a < nky; a++)
                for (int bb = 0; bb < nkx; bb++) {
                    int j = c * 9 + (ky0 + a) * 3 + (kx0 + bb);
                    s += (f == 0) ? base_w[co * 36 + j]
                                  : spline_w[(co * 36 + j) * 5 + (f - 1)];
                }
        }
        wsh[e] = s;
    }
    __syncthreads();

    // Phase B2: padding contribution vectors (features of v=0; relu(0)=0 but
    // spline bases at 0 are nonzero)
    if (tid < 64) {
        float f0[6];
        spline_feats(0.0f, f0);
        int co = tid & 3, pos = (tid >> 2) & 3, p = tid >> 4;
        float s = 0.0f;
#pragma unroll
        for (int c = 0; c < 4; c++)
#pragma unroll
            for (int f = 0; f < 6; f++)
                s += f0[f] * wsh[(((p * 4 + pos) * 4 + c) * 6 + f) * 4 + co];
        reinterpret_cast<float*>(psh4)[tid] = s;
    }
    __syncthreads();

    // Phase C: conv. One 2x2 output quad per thread.
    const int i = tid / S2;
    const int r = tid % S2;
    const int Y = r / HIN, X = r % HIN;

    float4 acc[4];
#pragma unroll
    for (int p = 0; p < 4; p++) acc[p] = make_float4(0.f, 0.f, 0.f, 0.f);

#pragma unroll
    for (int p = 0; p < 4; p++) {
        const int py = p >> 1, px = p & 1;
#pragma unroll
        for (int pos = 0; pos < 4; pos++) {
            const int ry = pos >> 1, rx = pos & 1;
            const int sy = Y - 1 + py + ry;
            const int sx = X - 1 + px + rx;
            if ((unsigned)sy < (unsigned)HIN && (unsigned)sx < (unsigned)HIN) {
                const float* fp = &feat[((i * 4) * S2 + sy * HIN + sx) * 7];
                const float4* wp = &wsh4[(p * 4 + pos) * 4 * 6];
#pragma unroll
                for (int c = 0; c < 4; c++) {
#pragma unroll
                    for (int f = 0; f < 6; f++) {
                        float  v = fp[c * S2 * 7 + f];
                        float4 w = wp[c * 6 + f];
                        acc[p].x = fmaf(v, w.x, acc[p].x);
                        acc[p].y = fmaf(v, w.y, acc[p].y);
                        acc[p].z = fmaf(v, w.z, acc[p].z);
                        acc[p].w = fmaf(v, w.w, acc[p].w);
                    }
                }
            } else {
                float4 pad = psh4[p * 4 + pos];
                acc[p].x += pad.x; acc[p].y += pad.y;
                acc[p].z += pad.z; acc[p].w += pad.w;
            }
        }
    }

    const int b = blockIdx.x * IMGS + i;
    const size_t obase = (size_t)b * COUT * HOUT * HOUT;
#pragma unroll
    for (int p = 0; p < 4; p++) {
        int y = 2 * Y + (p >> 1), x = 2 * X + (p & 1);
#pragma unroll
        for (int co = 0; co < COUT; co++) {
            float val = (co == 0) ? acc[p].x : (co == 1) ? acc[p].y
                       : (co == 2) ? acc[p].z : acc[p].w;
            if (FINAL) val = tanhf(val);
            hout[obase + (size_t)co * HOUT * HOUT + y * HOUT + x] = val;
        }
    }
}

// ---------------------------------------------------------------------------
extern "C" void kernel_launch(void* const* d_in, const int* in_sizes, int n_in,
                              void* d_out, int out_size) {
    const float* x     = (const float*)d_in[0];
    const float* lin_w = (const float*)d_in[1];
    const float* lin_b = (const float*)d_in[2];
    const float* bw1   = (const float*)d_in[3];
    const float* sw1   = (const float*)d_in[4];
    const float* bw2   = (const float*)d_in[5];
    const float* sw2   = (const float*)d_in[6];
    const float* bw3   = (const float*)d_in[7];
    const float* sw3   = (const float*)d_in[8];
    const float* bw4   = (const float*)d_in[9];
    const float* sw4   = (const float*)d_in[10];

    float *h0, *h1, *h2, *h3;
    cudaGetSymbolAddress((void**)&h0, g_h0);
    cudaGetSymbolAddress((void**)&h1, g_h1);
    cudaGetSymbolAddress((void**)&h2, g_h2);
    cudaGetSymbolAddress((void**)&h3, g_h3);

    lin_relu_kernel<<<32, 256>>>(x, lin_w, lin_b, h0);
    kan_stage_kernel<2, 4, false><<<8,   256>>>(h0, bw1, sw1, h1);
    kan_stage_kernel<4, 4, false><<<32,  256>>>(h1, bw2, sw2, h2);
    kan_stage_kernel<8, 4, false><<<128, 256>>>(h2, bw3, sw3, h3);
    kan_stage_kernel<16, 3, true><<<512, 256>>>(h3, bw4, sw4, (float*)d_out);
}

// round 3
// speedup vs baseline: 1.3153x; 1.3153x over previous
#include <cuda_runtime.h>
#include <math.h>

// ---------------------------------------------------------------------------
// Fully-fused KAN generator, one block per batch sample (512 blocks x 256 thr).
//   h0 = relu(x @ lin_w.T + lin_b)  -> SMEM act[16]   ([c][y][x], 4x2x2)
//   stage<2>  : up2 + kan_conv -> act[64]
//   stage<4>  : up2 + kan_conv -> act[256]
//   stage<8>  : up2 + kan_conv -> act[1024]
//   stage<16> : up2 + kan_conv -> tanh -> global out [3,32,32]
//
// Per-stage: per-source-value features computed once (relu + 5 quadratic
// B-spline bases); the 3x3 conv over up2() collapses to 4 parity-dependent
// combined-weight sets over the 2x2 distinct source pixels; zero-padding
// contributes spline(0) != 0 via precomputed pad vectors.
//
// Features split: featA=float4 (bases 0-3, conflict-free LDS.128),
//                 featB=float2 (base4, relu, conflict-free LDS.64).
// Combined weights wsh: [p][pos][c][f(6)] -> float4 over co.
// ---------------------------------------------------------------------------

__device__ __forceinline__ void spline_feats(float v, float4& fa, float2& fb) {
    const float H = 2.0f / 3.0f;
    float g[8];
#pragma unroll
    for (int i = 0; i < 8; i++) g[i] = (float)(i - 2) * H - 1.0f;
    float b0[7];
#pragma unroll
    for (int i = 0; i < 7; i++)
        b0[i] = (v >= g[i] && v < g[i + 1]) ? 1.0f : 0.0f;
    float b1[6];
#pragma unroll
    for (int i = 0; i < 6; i++)
        b1[i] = (v - g[i]) * (1.0f / (g[i + 1] - g[i])) * b0[i]
              + (g[i + 2] - v) * (1.0f / (g[i + 2] - g[i + 1])) * b0[i + 1];
    float b2[5];
#pragma unroll
    for (int i = 0; i < 5; i++)
        b2[i] = (v - g[i]) * (1.0f / (g[i + 2] - g[i])) * b1[i]
              + (g[i + 3] - v) * (1.0f / (g[i + 3] - g[i + 1])) * b1[i + 1];
    fa = make_float4(b2[0], b2[1], b2[2], b2[3]);
    fb = make_float2(b2[4], fmaxf(v, 0.0f));
}

__device__ __forceinline__ void fma4(float s, float4 w, float4& a) {
    a.x = fmaf(s, w.x, a.x);
    a.y = fmaf(s, w.y, a.y);
    a.z = fmaf(s, w.z, a.z);
    a.w = fmaf(s, w.w, a.w);
}

// ----------------------------- one conv stage ------------------------------
template <int HIN, int COUT, bool FINAL>
__device__ __forceinline__ void do_stage(
    const float* __restrict__ bw, const float* __restrict__ sw,
    float* act, float4* featA, float2* featB,
    float4* wsh4, float4* padsh, float* gout)
{
    constexpr int S2   = HIN * HIN;
    constexpr int NSRC = 4 * S2;
    constexpr int HOUT = 2 * HIN;
    constexpr int P    = 4 * S2;     // output pixels per parity-expanded image
    const int tid = threadIdx.x;
    float* wsh = reinterpret_cast<float*>(wsh4);

    // --- build combined weights: W[p][pos][c][wf][co], wf: 0-4 spline, 5 relu
#pragma unroll
    for (int k = 0; k < 6; k++) {
        int e   = tid + k * 256;
        int co  = e & 3;
        int wf  = (e >> 2) % 6;
        int c   = (e / 24) & 3;
        int pos = (e / 96) & 3;
        int p   = e / 384;
        int py = p >> 1, px = p & 1;
        int ry = pos >> 1, rx = pos & 1;
        float s = 0.0f;
        if (co < COUT) {
            int ky0 = ry * (1 + py), nky = 1 + (ry ^ py);
            int kx0 = rx * (1 + px), nkx = 1 + (rx ^ px);
            for (int a = 0; a < nky; a++)
                for (int bb = 0; bb < nkx; bb++) {
                    int j = c * 9 + (ky0 + a) * 3 + (kx0 + bb);
                    s += (wf == 5) ? bw[co * 36 + j]
                                   : sw[(co * 36 + j) * 5 + wf];
                }
        }
        wsh[e] = s;
    }

    // --- featurize source values (reads act)
#pragma unroll
    for (int k = 0; k < (NSRC + 255) / 256; k++) {
        int lv = tid + k * 256;
        if (NSRC >= 256 || lv < NSRC)
            spline_feats(act[lv], featA[lv], featB[lv]);
    }

    // --- pad vectors directly from raw weights (no wsh dependency)
    if (tid < 64) {
        float4 f0a; float2 f0b;
        spline_feats(0.0f, f0a, f0b);   // relu(0)=0
        float fv[5] = {f0a.x, f0a.y, f0a.z, f0a.w, f0b.x};
        int co = tid & 3, pos = (tid >> 2) & 3, p = tid >> 4;
        int py = p >> 1, px = p & 1;
        int ry = pos >> 1, rx = pos & 1;
        float s = 0.0f;
        if (co < COUT) {
            int ky0 = ry * (1 + py), nky = 1 + (ry ^ py);
            int kx0 = rx * (1 + px), nkx = 1 + (rx ^ px);
            for (int c = 0; c < 4; c++)
                for (int a = 0; a < nky; a++)
                    for (int bb = 0; bb < nkx; bb++) {
                        int j = c * 9 + (ky0 + a) * 3 + (kx0 + bb);
#pragma unroll
                        for (int wf = 0; wf < 5; wf++)
                            s += fv[wf] * sw[(co * 36 + j) * 5 + wf];
                    }
        }
        reinterpret_cast<float*>(padsh)[tid] = s;
    }
    __syncthreads();

    // --- phase C: each work item = one output pixel (all COUT channels)
#pragma unroll 1
    for (int it = 0; it < (P + 255) / 256; it++) {
        int pix = tid + it * 256;
        if (P >= 256 || pix < P) {
            int p = pix / S2;
            int q = pix & (S2 - 1);
            int Y = q / HIN, X = q & (HIN - 1);
            int py = p >> 1, px = p & 1;
            float4 acc = make_float4(0.f, 0.f, 0.f, 0.f);
#pragma unroll
            for (int pos = 0; pos < 4; pos++) {
                int sy = Y - 1 + py + (pos >> 1);
                int sx = X - 1 + px + (pos & 1);
                const float4* wp = wsh4 + (p * 4 + pos) * 24;
                if ((unsigned)sy < (unsigned)HIN && (unsigned)sx < (unsigned)HIN) {
                    int base = sy * HIN + sx;
#pragma unroll
                    for (int c = 0; c < 4; c++) {
                        float4 fa = featA[c * S2 + base];
                        float2 fb = featB[c * S2 + base];
                        const float4* w = wp + c * 6;
                        fma4(fa.x, w[0], acc);
                        fma4(fa.y, w[1], acc);
                        fma4(fa.z, w[2], acc);
                        fma4(fa.w, w[3], acc);
                        fma4(fb.x, w[4], acc);
                        fma4(fb.y, w[5], acc);
                    }
                } else {
                    float4 pd = padsh[p * 4 + pos];
                    acc.x += pd.x; acc.y += pd.y; acc.z += pd.z; acc.w += pd.w;
                }
            }
            int y = 2 * Y + py, xo = 2 * X + px;
            if (FINAL) {
                gout[0 * HOUT * HOUT + y * HOUT + xo] = tanhf(acc.x);
                gout[1 * HOUT * HOUT + y * HOUT + xo] = tanhf(acc.y);
                gout[2 * HOUT * HOUT + y * HOUT + xo] = tanhf(acc.z);
            } else {
                act[0 * HOUT * HOUT + y * HOUT + xo] = acc.x;
                act[1 * HOUT * HOUT + y * HOUT + xo] = acc.y;
                act[2 * HOUT * HOUT + y * HOUT + xo] = acc.z;
                act[3 * HOUT * HOUT + y * HOUT + xo] = acc.w;
            }
        }
    }
    __syncthreads();   // act/wsh/feat stable before next stage
}

// ----------------------------- fused kernel --------------------------------
__global__ void __launch_bounds__(256, 4) fused_kan_kernel(
    const float* __restrict__ x,
    const float* __restrict__ lin_w,
    const float* __restrict__ lin_b,
    const float* __restrict__ bw1, const float* __restrict__ sw1,
    const float* __restrict__ bw2, const float* __restrict__ sw2,
    const float* __restrict__ bw3, const float* __restrict__ sw3,
    const float* __restrict__ bw4, const float* __restrict__ sw4,
    float* __restrict__ out)
{
    __shared__ float  act[1024];
    __shared__ float4 featA[1024];
    __shared__ float2 featB[1024];
    __shared__ float4 wsh4[384];
    __shared__ float4 padsh[16];

    const int tid = threadIdx.x;
    const int b   = blockIdx.x;

    // linear + relu: 16 outputs, 4 threads each over 25-element chunks
    if (tid < 64) {
        int j = tid >> 2, qp = tid & 3;
        const float* xr = x + b * 100 + qp * 25;
        const float* wr = lin_w + j * 100 + qp * 25;
        float acc = 0.0f;
#pragma unroll
        for (int i = 0; i < 25; i++) acc = fmaf(xr[i], wr[i], acc);
        acc += __shfl_xor_sync(0xffffffffu, acc, 1);
        acc += __shfl_xor_sync(0xffffffffu, acc, 2);
        if (qp == 0) act[j] = fmaxf(acc + lin_b[j], 0.0f);
    }
    __syncthreads();

    do_stage<2, 4, false>(bw1, sw1, act, featA, featB, wsh4, padsh, nullptr);
    do_stage<4, 4, false>(bw2, sw2, act, featA, featB, wsh4, padsh, nullptr);
    do_stage<8, 4, false>(bw3, sw3, act, featA, featB, wsh4, padsh, nullptr);
    do_stage<16, 3, true>(bw4, sw4, act, featA, featB, wsh4, padsh,
                          out + (size_t)b * 3 * 32 * 32);
}

// ---------------------------------------------------------------------------
extern "C" void kernel_launch(void* const* d_in, const int* in_sizes, int n_in,
                              void* d_out, int out_size) {
    const float* x     = (const float*)d_in[0];
    const float* lin_w = (const float*)d_in[1];
    const float* lin_b = (const float*)d_in[2];
    const float* bw1   = (const float*)d_in[3];
    const float* sw1   = (const float*)d_in[4];
    const float* bw2   = (const float*)d_in[5];
    const float* sw2   = (const float*)d_in[6];
    const float* bw3   = (const float*)d_in[7];
    const float* sw3   = (const float*)d_in[8];
    const float* bw4   = (const float*)d_in[9];
    const float* sw4   = (const float*)d_in[10];

    fused_kan_kernel<<<512, 256>>>(x, lin_w, lin_b,
                                   bw1, sw1, bw2, sw2, bw3, sw3, bw4, sw4,
                                   (float*)d_out);
}

// round 4
// speedup vs baseline: 1.7848x; 1.3570x over previous
#include <cuda_runtime.h>
#include <math.h>

// ---------------------------------------------------------------------------
// Fully-fused KAN generator, one block per batch sample (512 blocks x 256 thr).
//   h0 = relu(x @ lin_w.T + lin_b)  -> SMEM act[16]   ([c][y][x], 4x2x2)
//   stage<2>  : up2 + kan_conv -> act[64]
//   stage<4>  : up2 + kan_conv -> act[256]
//   stage<8>  : up2 + kan_conv -> act[1024]
//   stage<16> : up2 + kan_conv -> tanh -> global out [3,32,32]
//
// Phase C retiled: parity p = tid>>6 is warp-uniform; each 64-lane group
// covers its parity's S2 pixels with NPX = S2/64 pixels per thread, so every
// warp-uniform weight float4 is loaded ONCE per NPX pixels (weight LDS /4 for
// the dominant stage). Out-of-bounds source pixels use compile-time
// spline(0) feature constants instead of pad vectors.
// ---------------------------------------------------------------------------

// quadratic B-spline bases evaluated at v=0 (exact to fp32 rounding):
// b2 = {0, 1/8, 3/4, 1/8, 0}, relu(0) = 0
#define F0A make_float4(0.0f, 0.125f, 0.75f, 0.125f)
#define F0B make_float2(0.0f, 0.0f)

__device__ __forceinline__ void spline_feats(float v, float4& fa, float2& fb) {
    const float H = 2.0f / 3.0f;
    float g[8];
#pragma unroll
    for (int i = 0; i < 8; i++) g[i] = (float)(i - 2) * H - 1.0f;
    float b0[7];
#pragma unroll
    for (int i = 0; i < 7; i++)
        b0[i] = (v >= g[i] && v < g[i + 1]) ? 1.0f : 0.0f;
    float b1[6];
#pragma unroll
    for (int i = 0; i < 6; i++)
        b1[i] = (v - g[i]) * (1.0f / (g[i + 1] - g[i])) * b0[i]
              + (g[i + 2] - v) * (1.0f / (g[i + 2] - g[i + 1])) * b0[i + 1];
    float b2[5];
#pragma unroll
    for (int i = 0; i < 5; i++)
        b2[i] = (v - g[i]) * (1.0f / (g[i + 2] - g[i])) * b1[i]
              + (g[i + 3] - v) * (1.0f / (g[i + 3] - g[i + 1])) * b1[i + 1];
    fa = make_float4(b2[0], b2[1], b2[2], b2[3]);
    fb = make_float2(b2[4], fmaxf(v, 0.0f));
}

__device__ __forceinline__ void fma4(float s, float4 w, float4& a) {
    a.x = fmaf(s, w.x, a.x);
    a.y = fmaf(s, w.y, a.y);
    a.z = fmaf(s, w.z, a.z);
    a.w = fmaf(s, w.w, a.w);
}

// ----------------------------- one conv stage ------------------------------
template <int HIN, int COUT, bool FINAL>
__device__ __forceinline__ void do_stage(
    const float* __restrict__ bw, const float* __restrict__ sw,
    float* act, float4* featA, float2* featB,
    float4* wsh4, float* gout)
{
    constexpr int S2   = HIN * HIN;
    constexpr int NSRC = 4 * S2;
    constexpr int HOUT = 2 * HIN;
    constexpr int NPX  = (S2 > 64) ? S2 / 64 : 1;  // pixels per thread
    const int tid = threadIdx.x;
    float* wsh = reinterpret_cast<float*>(wsh4);

    // --- build combined weights: W[p][pos][c][wf][co], wf: 0-4 spline, 5 relu
#pragma unroll
    for (int k = 0; k < 6; k++) {
        int e   = tid + k * 256;
        int co  = e & 3;
        int wf  = (e >> 2) % 6;
        int c   = (e / 24) & 3;
        int pos = (e / 96) & 3;
        int p   = e / 384;
        int py = p >> 1, px = p & 1;
        int ry = pos >> 1, rx = pos & 1;
        float s = 0.0f;
        if (co < COUT) {
            int ky0 = ry * (1 + py), nky = 1 + (ry ^ py);
            int kx0 = rx * (1 + px), nkx = 1 + (rx ^ px);
            for (int a = 0; a < nky; a++)
                for (int bb = 0; bb < nkx; bb++) {
                    int j = c * 9 + (ky0 + a) * 3 + (kx0 + bb);
                    s += (wf == 5) ? bw[co * 36 + j]
                                   : sw[(co * 36 + j) * 5 + wf];
                }
        }
        wsh[e] = s;
    }

    // --- featurize source values (reads act)
#pragma unroll
    for (int k = 0; k < (NSRC + 255) / 256; k++) {
        int lv = tid + k * 256;
        if (NSRC >= 256 || lv < NSRC)
            spline_feats(act[lv], featA[lv], featB[lv]);
    }
    __syncthreads();

    // --- phase C: parity-group tiling, NPX pixels per thread, weights
    //     loaded once per NPX pixels (warp-uniform broadcast)
    const int p  = tid >> 6;       // warp-uniform parity
    const int l  = tid & 63;
    const int py = p >> 1, px = p & 1;

    if (S2 >= 64 || l < S2) {
        const int Yb = l / HIN;    // base row for this thread
        const int X  = l % HIN;    // column (same for all NPX pixels)
        float4 acc[NPX];
#pragma unroll
        for (int j = 0; j < NPX; j++) acc[j] = make_float4(0.f, 0.f, 0.f, 0.f);

#pragma unroll
        for (int pos = 0; pos < 4; pos++) {
            const int ry = pos >> 1, rx = pos & 1;
            const int sx = X - 1 + px + rx;
            const bool vx = (unsigned)sx < (unsigned)HIN;
            int  syj[NPX];
            bool vj[NPX];
#pragma unroll
            for (int j = 0; j < NPX; j++) {
                syj[j] = Yb + j * (64 / HIN) - 1 + py + ry;
                vj[j]  = vx && ((unsigned)syj[j] < (unsigned)HIN);
            }
            const float4* wp = wsh4 + (p * 4 + pos) * 24;
#pragma unroll
            for (int c = 0; c < 4; c++) {
                float4 fa[NPX];
                float2 fb[NPX];
#pragma unroll
                for (int j = 0; j < NPX; j++) {
                    if (vj[j]) {
                        int idx = c * S2 + syj[j] * HIN + sx;
                        fa[j] = featA[idx];
                        fb[j] = featB[idx];
                    } else {
                        fa[j] = F0A;      // spline(0) bases, relu(0)=0
                        fb[j] = F0B;
                    }
                }
                const float4* w = wp + c * 6;
#pragma unroll
                for (int f = 0; f < 6; f++) {
                    float4 wv = w[f];
#pragma unroll
                    for (int j = 0; j < NPX; j++) {
                        float s = (f == 0) ? fa[j].x : (f == 1) ? fa[j].y
                                : (f == 2) ? fa[j].z : (f == 3) ? fa[j].w
                                : (f == 4) ? fb[j].x : fb[j].y;
                        fma4(s, wv, acc[j]);
                    }
                }
            }
        }

        // --- write outputs
#pragma unroll
        for (int j = 0; j < NPX; j++) {
            int q = l + 64 * j;
            int Y = q / HIN, Xo = q % HIN;
            int y = 2 * Y + py, x = 2 * Xo + px;
            if (FINAL) {
                gout[0 * HOUT * HOUT + y * HOUT + x] = tanhf(acc[j].x);
                gout[1 * HOUT * HOUT + y * HOUT + x] = tanhf(acc[j].y);
                gout[2 * HOUT * HOUT + y * HOUT + x] = tanhf(acc[j].z);
            } else {
                act[0 * HOUT * HOUT + y * HOUT + x] = acc[j].x;
                act[1 * HOUT * HOUT + y * HOUT + x] = acc[j].y;
                act[2 * HOUT * HOUT + y * HOUT + x] = acc[j].z;
                act[3 * HOUT * HOUT + y * HOUT + x] = acc[j].w;
            }
        }
    }
    __syncthreads();   // act/wsh/feat stable before next stage
}

// ----------------------------- fused kernel --------------------------------
__global__ void __launch_bounds__(256) fused_kan_kernel(
    const float* __restrict__ x,
    const float* __restrict__ lin_w,
    const float* __restrict__ lin_b,
    const float* __restrict__ bw1, const float* __restrict__ sw1,
    const float* __restrict__ bw2, const float* __restrict__ sw2,
    const float* __restrict__ bw3, const float* __restrict__ sw3,
    const float* __restrict__ bw4, const float* __restrict__ sw4,
    float* __restrict__ out)
{
    __shared__ float  act[1024];
    __shared__ float4 featA[1024];
    __shared__ float2 featB[1024];
    __shared__ float4 wsh4[384];

    const int tid = threadIdx.x;
    const int b   = blockIdx.x;

    // linear + relu: 16 outputs, 4 threads each over 25-element chunks
    if (tid < 64) {
        int j = tid >> 2, qp = tid & 3;
        const float* xr = x + b * 100 + qp * 25;
        const float* wr = lin_w + j * 100 + qp * 25;
        float acc = 0.0f;
#pragma unroll
        for (int i = 0; i < 25; i++) acc = fmaf(xr[i], wr[i], acc);
        acc += __shfl_xor_sync(0xffffffffu, acc, 1);
        acc += __shfl_xor_sync(0xffffffffu, acc, 2);
        if (qp == 0) act[j] = fmaxf(acc + lin_b[j], 0.0f);
    }
    __syncthreads();

    do_stage<2, 4, false>(bw1, sw1, act, featA, featB, wsh4, nullptr);
    do_stage<4, 4, false>(bw2, sw2, act, featA, featB, wsh4, nullptr);
    do_stage<8, 4, false>(bw3, sw3, act, featA, featB, wsh4, nullptr);
    do_stage<16, 3, true>(bw4, sw4, act, featA, featB, wsh4,
                          out + (size_t)b * 3 * 32 * 32);
}

// ---------------------------------------------------------------------------
extern "C" void kernel_launch(void* const* d_in, const int* in_sizes, int n_in,
                              void* d_out, int out_size) {
    const float* x     = (const float*)d_in[0];
    const float* lin_w = (const float*)d_in[1];
    const float* lin_b = (const float*)d_in[2];
    const float* bw1   = (const float*)d_in[3];
    const float* sw1   = (const float*)d_in[4];
    const float* bw2   = (const float*)d_in[5];
    const float* sw2   = (const float*)d_in[6];
    const float* bw3   = (const float*)d_in[7];
    const float* sw3   = (const float*)d_in[8];
    const float* bw4   = (const float*)d_in[9];
    const float* sw4   = (const float*)d_in[10];

    fused_kan_kernel<<<512, 256>>>(x, lin_w, lin_b,
                                   bw1, sw1, bw2, sw2, bw3, sw3, bw4, sw4,
                                   (float*)d_out);
}